// round 15
// baseline (speedup 1.0000x reference)
#include <cuda_runtime.h>
#include <cuda_bf16.h>
#include <math.h>

// ---------------------------------------------------------------------------
// VQ-VAE forward on GB300 (sm_103a). Round 14: 3xTF32 GEMMs with the hi/lo
// split HOISTED into smem staging (inner loop = pure LDS+MMA).
//   h1'  = relu(x @ W1 + b1)     [3xTF32 TC]
//   z_e' = h1' @ W2 + b2         [3xTF32 TC] -> output region 2
//   VQ on z_e': argmin + top-2 gap; slots with gap < THETA flagged
//   repair: flagged slots recomputed with the EXACT scalar fp32 chain
//   h3   = relu(b3 + sum_n P[n,idx[b,n],:])   (P-table; GEMM3 eliminated)
//   recon= tanh(h3 @ W4 + b4)    [3xTF32 TC] -> output region 1
// Output layout: recon | z_e | emb  (fp32, concatenated)
// ---------------------------------------------------------------------------

#define Bsz    32768
#define IN_DIM 784
#define H0     512
#define H1     1024
#define Kc     128
#define Dd     128
#define Nn     8
#define THETA  4e-3f

// Scratch (__device__ globals; no allocation allowed)
__device__ __align__(16) float g_h1[Bsz * H0];            // 64 MB
__device__ __align__(16) float g_h3[Bsz * H0];            // 64 MB
__device__ __align__(16) float g_P[Nn * Kc * H0];         // 2 MB
__device__ int   g_idx[Bsz * Nn];                         // 1 MB
__device__ int   g_nrep;
__device__ int   g_replist[Bsz * Nn];

// ---------------------------------------------------------------------------
// 3xTF32 tensor-core GEMM, split-at-staging.
// Block tile 128x64xBK16, 256 thr = 8 warps (4m x 2n), warp tile 32x32.
// Smem (dynamic, 59.4KB): As_hi/As_lo [2][128][20], Bs_hi/Bs_lo [2][16][72].
// M%128==0, K%16==0, N%4==0 (N edge guarded). ACT: 0=none,1=relu,2=tanh
// ---------------------------------------------------------------------------
#define AS_STRIDE 20
#define BS_STRIDE 72
#define AS_BUF (128 * AS_STRIDE)              // 2560 floats per buffer
#define BS_BUF (16 * BS_STRIDE)               // 1152 floats per buffer
#define OFF_AHI 0
#define OFF_ALO (2 * AS_BUF)
#define OFF_BHI (4 * AS_BUF)
#define OFF_BLO (4 * AS_BUF + 2 * BS_BUF)
#define GEMM_SMEM ((4 * AS_BUF + 4 * BS_BUF) * (int)sizeof(float))  // 59392 B

__device__ __forceinline__ void split_tf32(float a, float& hi, float& lo) {
    unsigned h;
    asm("cvt.rna.tf32.f32 %0, %1;" : "=r"(h) : "f"(a));
    float hf = __uint_as_float(h);
    float l = a - hf;
    unsigned lr;
    asm("cvt.rna.tf32.f32 %0, %1;" : "=r"(lr) : "f"(l));
    hi = hf; lo = __uint_as_float(lr);
}

__device__ __forceinline__ void split4(float4 v, float4& hi, float4& lo) {
    split_tf32(v.x, hi.x, lo.x);
    split_tf32(v.y, hi.y, lo.y);
    split_tf32(v.z, hi.z, lo.z);
    split_tf32(v.w, hi.w, lo.w);
}

__device__ __forceinline__ void mma_tf32(float4& d, const unsigned* a, const unsigned* b) {
    asm("mma.sync.aligned.m16n8k8.row.col.f32.tf32.tf32.f32 "
        "{%0,%1,%2,%3}, {%4,%5,%6,%7}, {%8,%9}, {%0,%1,%2,%3};"
        : "+f"(d.x), "+f"(d.y), "+f"(d.z), "+f"(d.w)
        : "r"(a[0]), "r"(a[1]), "r"(a[2]), "r"(a[3]), "r"(b[0]), "r"(b[1]));
}

template <int ACT>
__global__ __launch_bounds__(256, 2)
void gemm_tc(const float* __restrict__ A, const float* __restrict__ W,
             const float* __restrict__ bias, float* __restrict__ C,
             int M, int N, int K)
{
    extern __shared__ float smem[];
    float* As_hi = smem + OFF_AHI;   // [2][128][20]
    float* As_lo = smem + OFF_ALO;
    float* Bs_hi = smem + OFF_BHI;   // [2][16][72]
    float* Bs_lo = smem + OFF_BLO;

    const int tid  = threadIdx.x;
    const int warp = tid >> 5;
    const int lane = tid & 31;
    const int gid  = lane >> 2;
    const int tig  = lane & 3;

    const int m0 = blockIdx.y * 128;
    const int n0 = blockIdx.x * 64;
    const int wm = (warp >> 1) * 32;
    const int wn = (warp & 1) * 32;

    const int a_row = tid >> 2;
    const int a_q   = (tid & 3) * 4;
    const int b_row = tid >> 4;
    const int b_q   = (tid & 15) * 4;
    const bool b_ok = (n0 + b_q < N);

    float4 acc[2][4];
#pragma unroll
    for (int mt = 0; mt < 2; ++mt)
#pragma unroll
        for (int nt = 0; nt < 4; ++nt)
            acc[mt][nt] = make_float4(0.f, 0.f, 0.f, 0.f);

    const int nsteps = K / 16;

    // prologue: load + split k-step 0 into buffer 0
    {
        float4 av0 = *reinterpret_cast<const float4*>(&A[(size_t)(m0 + a_row) * K + a_q]);
        float4 av1 = *reinterpret_cast<const float4*>(&A[(size_t)(m0 + 64 + a_row) * K + a_q]);
        float4 bv  = make_float4(0.f, 0.f, 0.f, 0.f);
        if (b_ok)
            bv = *reinterpret_cast<const float4*>(&W[(size_t)b_row * N + n0 + b_q]);
        float4 h, l;
        split4(av0, h, l);
        *reinterpret_cast<float4*>(&As_hi[a_row * AS_STRIDE + a_q]) = h;
        *reinterpret_cast<float4*>(&As_lo[a_row * AS_STRIDE + a_q]) = l;
        split4(av1, h, l);
        *reinterpret_cast<float4*>(&As_hi[(64 + a_row) * AS_STRIDE + a_q]) = h;
        *reinterpret_cast<float4*>(&As_lo[(64 + a_row) * AS_STRIDE + a_q]) = l;
        split4(bv, h, l);
        *reinterpret_cast<float4*>(&Bs_hi[b_row * BS_STRIDE + b_q]) = h;
        *reinterpret_cast<float4*>(&Bs_lo[b_row * BS_STRIDE + b_q]) = l;
    }
    __syncthreads();

    for (int s = 0; s < nsteps; ++s) {
        const int cur = s & 1;
        const bool more = (s + 1 < nsteps);

        float4 av0, av1, bv;
        if (more) {
            const int k0 = (s + 1) * 16;
            av0 = *reinterpret_cast<const float4*>(&A[(size_t)(m0 + a_row) * K + k0 + a_q]);
            av1 = *reinterpret_cast<const float4*>(&A[(size_t)(m0 + 64 + a_row) * K + k0 + a_q]);
            bv  = make_float4(0.f, 0.f, 0.f, 0.f);
            if (b_ok)
                bv = *reinterpret_cast<const float4*>(&W[(size_t)(k0 + b_row) * N + n0 + b_q]);
        }

        const float* ah = As_hi + cur * AS_BUF;
        const float* al = As_lo + cur * AS_BUF;
        const float* bh = Bs_hi + cur * BS_BUF;
        const float* bl = Bs_lo + cur * BS_BUF;

#pragma unroll
        for (int k8 = 0; k8 < 16; k8 += 8) {
            unsigned ahi[2][4], alo[2][4];
#pragma unroll
            for (int mt = 0; mt < 2; ++mt) {
                const int rb = wm + mt * 16;
                ahi[mt][0] = __float_as_uint(ah[(rb + gid)     * AS_STRIDE + k8 + tig]);
                ahi[mt][1] = __float_as_uint(ah[(rb + gid + 8) * AS_STRIDE + k8 + tig]);
                ahi[mt][2] = __float_as_uint(ah[(rb + gid)     * AS_STRIDE + k8 + tig + 4]);
                ahi[mt][3] = __float_as_uint(ah[(rb + gid + 8) * AS_STRIDE + k8 + tig + 4]);
                alo[mt][0] = __float_as_uint(al[(rb + gid)     * AS_STRIDE + k8 + tig]);
                alo[mt][1] = __float_as_uint(al[(rb + gid + 8) * AS_STRIDE + k8 + tig]);
                alo[mt][2] = __float_as_uint(al[(rb + gid)     * AS_STRIDE + k8 + tig + 4]);
                alo[mt][3] = __float_as_uint(al[(rb + gid + 8) * AS_STRIDE + k8 + tig + 4]);
            }
            unsigned bhi[4][2], blo[4][2];
#pragma unroll
            for (int nt = 0; nt < 4; ++nt) {
                const int cb = wn + nt * 8 + gid;
                bhi[nt][0] = __float_as_uint(bh[(k8 + tig)     * BS_STRIDE + cb]);
                bhi[nt][1] = __float_as_uint(bh[(k8 + tig + 4) * BS_STRIDE + cb]);
                blo[nt][0] = __float_as_uint(bl[(k8 + tig)     * BS_STRIDE + cb]);
                blo[nt][1] = __float_as_uint(bl[(k8 + tig + 4) * BS_STRIDE + cb]);
            }
#pragma unroll
            for (int mt = 0; mt < 2; ++mt)
#pragma unroll
                for (int nt = 0; nt < 4; ++nt) {
                    mma_tf32(acc[mt][nt], alo[mt], bhi[nt]);
                    mma_tf32(acc[mt][nt], ahi[mt], blo[nt]);
                    mma_tf32(acc[mt][nt], ahi[mt], bhi[nt]);
                }
        }

        if (more) {
            const int nxt = cur ^ 1;
            float4 h, l;
            split4(av0, h, l);
            *reinterpret_cast<float4*>(&As_hi[nxt * AS_BUF + a_row * AS_STRIDE + a_q]) = h;
            *reinterpret_cast<float4*>(&As_lo[nxt * AS_BUF + a_row * AS_STRIDE + a_q]) = l;
            split4(av1, h, l);
            *reinterpret_cast<float4*>(&As_hi[nxt * AS_BUF + (64 + a_row) * AS_STRIDE + a_q]) = h;
            *reinterpret_cast<float4*>(&As_lo[nxt * AS_BUF + (64 + a_row) * AS_STRIDE + a_q]) = l;
            split4(bv, h, l);
            *reinterpret_cast<float4*>(&Bs_hi[nxt * BS_BUF + b_row * BS_STRIDE + b_q]) = h;
            *reinterpret_cast<float4*>(&Bs_lo[nxt * BS_BUF + b_row * BS_STRIDE + b_q]) = l;
        }
        __syncthreads();
    }

    // epilogue: bias + activation
#pragma unroll
    for (int mt = 0; mt < 2; ++mt) {
        const int r0 = m0 + wm + mt * 16 + gid;
        const int r1 = r0 + 8;
#pragma unroll
        for (int nt = 0; nt < 4; ++nt) {
            const int c0 = n0 + wn + nt * 8 + 2 * tig;
            const int c1 = c0 + 1;
            if (c0 < N) {
                const float bb = bias[c0];
                float u = __fadd_rn(acc[mt][nt].x, bb);
                float v = __fadd_rn(acc[mt][nt].z, bb);
                if (ACT == 1) { u = fmaxf(u, 0.f); v = fmaxf(v, 0.f); }
                if (ACT == 2) { u = tanhf(u); v = tanhf(v); }
                C[(size_t)r0 * N + c0] = u;
                C[(size_t)r1 * N + c0] = v;
            }
            if (c1 < N) {
                const float bb = bias[c1];
                float u = __fadd_rn(acc[mt][nt].y, bb);
                float v = __fadd_rn(acc[mt][nt].w, bb);
                if (ACT == 1) { u = fmaxf(u, 0.f); v = fmaxf(v, 0.f); }
                if (ACT == 2) { u = tanhf(u); v = tanhf(v); }
                C[(size_t)r0 * N + c1] = u;
                C[(size_t)r1 * N + c1] = v;
            }
        }
    }
}

// ---------------------------------------------------------------------------
__global__ void zero_nrep() { if (threadIdx.x == 0) g_nrep = 0; }

// ---------------------------------------------------------------------------
// Fused VQ with top-2 gap flagging (unchanged from passing R13).
// ---------------------------------------------------------------------------
#define VQ_SAMPLES 8
#define VQ_SMEM ((Kc * Dd + VQ_SAMPLES * H1 + Kc) * (int)sizeof(float))

__global__ __launch_bounds__(256, 2)
void vq_kernel(const float* __restrict__ z_e, const float* __restrict__ E,
               float* __restrict__ emb, int* __restrict__ idx_out)
{
    extern __shared__ float sh[];
    float* E_sh  = sh;
    float* z_sh  = sh + Kc * Dd;
    float* e2_sh = z_sh + VQ_SAMPLES * H1;

    const int tid  = threadIdx.x;
    const int warp = tid >> 5;
    const int lane = tid & 31;
    const size_t b0 = (size_t)blockIdx.x * VQ_SAMPLES;

#pragma unroll
    for (int i = 0; i < (Kc * Dd / 4) / 256; ++i)
        reinterpret_cast<float4*>(E_sh)[tid + i * 256] =
            reinterpret_cast<const float4*>(E)[tid + i * 256];
#pragma unroll
    for (int i = 0; i < (VQ_SAMPLES * H1 / 4) / 256; ++i)
        reinterpret_cast<float4*>(z_sh)[tid + i * 256] =
            reinterpret_cast<const float4*>(z_e + b0 * H1)[tid + i * 256];
    __syncthreads();

    if (tid < Kc) {
        float s = 0.f;
#pragma unroll 16
        for (int d = 0; d < Dd; ++d) {
            float v = E_sh[d * Kc + tid];
            s = __fadd_rn(s, __fmul_rn(v, v));
        }
        e2_sh[tid] = s;
    }
    __syncthreads();

    const int s = warp;
    const float* zrow = z_sh + s * H1;

    float s2 = 0.f;
    {
        const int n = lane & 7;
#pragma unroll 16
        for (int d = 0; d < Dd; ++d) {
            float v = zrow[d * 8 + n];
            s2 = __fadd_rn(s2, __fmul_rn(v, v));
        }
    }
    float z2v[Nn];
#pragma unroll
    for (int n = 0; n < Nn; ++n)
        z2v[n] = __shfl_sync(0xFFFFFFFFu, s2, n);

    float acc[Nn][4];
#pragma unroll
    for (int n = 0; n < Nn; ++n)
#pragma unroll
        for (int j = 0; j < 4; ++j) acc[n][j] = 0.f;

#pragma unroll 4
    for (int d = 0; d < Dd; ++d) {
        float4 ev = *reinterpret_cast<const float4*>(&E_sh[d * Kc + lane * 4]);
        float4 za = *reinterpret_cast<const float4*>(&zrow[d * 8]);
        float4 zb = *reinterpret_cast<const float4*>(&zrow[d * 8 + 4]);
        acc[0][0] = fmaf(za.x, ev.x, acc[0][0]); acc[0][1] = fmaf(za.x, ev.y, acc[0][1]);
        acc[0][2] = fmaf(za.x, ev.z, acc[0][2]); acc[0][3] = fmaf(za.x, ev.w, acc[0][3]);
        acc[1][0] = fmaf(za.y, ev.x, acc[1][0]); acc[1][1] = fmaf(za.y, ev.y, acc[1][1]);
        acc[1][2] = fmaf(za.y, ev.z, acc[1][2]); acc[1][3] = fmaf(za.y, ev.w, acc[1][3]);
        acc[2][0] = fmaf(za.z, ev.x, acc[2][0]); acc[2][1] = fmaf(za.z, ev.y, acc[2][1]);
        acc[2][2] = fmaf(za.z, ev.z, acc[2][2]); acc[2][3] = fmaf(za.z, ev.w, acc[2][3]);
        acc[3][0] = fmaf(za.w, ev.x, acc[3][0]); acc[3][1] = fmaf(za.w, ev.y, acc[3][1]);
        acc[3][2] = fmaf(za.w, ev.z, acc[3][2]); acc[3][3] = fmaf(za.w, ev.w, acc[3][3]);
        acc[4][0] = fmaf(zb.x, ev.x, acc[4][0]); acc[4][1] = fmaf(zb.x, ev.y, acc[4][1]);
        acc[4][2] = fmaf(zb.x, ev.z, acc[4][2]); acc[4][3] = fmaf(zb.x, ev.w, acc[4][3]);
        acc[5][0] = fmaf(zb.y, ev.x, acc[5][0]); acc[5][1] = fmaf(zb.y, ev.y, acc[5][1]);
        acc[5][2] = fmaf(zb.y, ev.z, acc[5][2]); acc[5][3] = fmaf(zb.y, ev.w, acc[5][3]);
        acc[6][0] = fmaf(zb.z, ev.x, acc[6][0]); acc[6][1] = fmaf(zb.z, ev.y, acc[6][1]);
        acc[6][2] = fmaf(zb.z, ev.z, acc[6][2]); acc[6][3] = fmaf(zb.z, ev.w, acc[6][3]);
        acc[7][0] = fmaf(zb.w, ev.x, acc[7][0]); acc[7][1] = fmaf(zb.w, ev.y, acc[7][1]);
        acc[7][2] = fmaf(zb.w, ev.z, acc[7][2]); acc[7][3] = fmaf(zb.w, ev.w, acc[7][3]);
    }

    const float4 e4 = *reinterpret_cast<const float4*>(&e2_sh[lane * 4]);

    int bi_arr[Nn];
#pragma unroll
    for (int n = 0; n < Nn; ++n) {
        const float z2n = z2v[n];
        float v[4];
        v[0] = __fadd_rn(fmaf(-2.0f, acc[n][0], z2n), e4.x);
        v[1] = __fadd_rn(fmaf(-2.0f, acc[n][1], z2n), e4.y);
        v[2] = __fadd_rn(fmaf(-2.0f, acc[n][2], z2n), e4.z);
        v[3] = __fadd_rn(fmaf(-2.0f, acc[n][3], z2n), e4.w);

        float best = v[0]; int bi = lane * 4;
        float sec  = 3.4e38f;
#pragma unroll
        for (int j = 1; j < 4; ++j) {
            if (v[j] < best) { sec = best; best = v[j]; bi = lane * 4 + j; }
            else             { sec = fminf(sec, v[j]); }
        }
#pragma unroll
        for (int off = 16; off > 0; off >>= 1) {
            float ov = __shfl_xor_sync(0xFFFFFFFFu, best, off);
            int   oi = __shfl_xor_sync(0xFFFFFFFFu, bi,  off);
            float os = __shfl_xor_sync(0xFFFFFFFFu, sec, off);
            if (ov < best || (ov == best && oi < bi)) {
                sec = fminf(best, os);
                best = ov; bi = oi;
            } else {
                sec = fminf(sec, fminf(ov, os));
            }
        }
        bi_arr[n] = bi;
        if (lane == n && (sec - best) < THETA) {
            int pos = atomicAdd(&g_nrep, 1);
            g_replist[pos] = (int)(b0 + s) * Nn + n;
        }
    }

    int bsel = bi_arr[0];
#pragma unroll
    for (int n = 1; n < Nn; ++n)
        if ((lane & 7) == n) bsel = bi_arr[n];

    if (lane < Nn)
        idx_out[(b0 + s) * Nn + lane] = bsel;

    float* erow = emb + (b0 + s) * H1;
#pragma unroll
    for (int t = 0; t < H1 / 32; ++t) {
        int i = t * 32 + lane;
        erow[i] = E_sh[(i >> 3) * Kc + bsel];
    }
}

// ---------------------------------------------------------------------------
// Repair: exact scalar fp32 chain for flagged slots (unchanged from R13).
// ---------------------------------------------------------------------------
__global__ __launch_bounds__(256, 4)
void repair_kernel(const float* __restrict__ x,  const float* __restrict__ W1,
                   const float* __restrict__ b1, const float* __restrict__ W2,
                   const float* __restrict__ b2, const float* __restrict__ E,
                   float* __restrict__ emb, int* __restrict__ idx_out)
{
    __shared__ float xrow[IN_DIM];
    __shared__ float h1row[H0];
    __shared__ float zrow[Dd];
    __shared__ float dist[Kc];
    __shared__ float z2_sh;
    __shared__ int   kbest_sh;

    const int tid = threadIdx.x;
    const int nrep = g_nrep;

    for (int r = blockIdx.x; r < nrep; r += gridDim.x) {
        const int slot = g_replist[r];
        const int b = slot >> 3;
        const int n = slot & 7;

        for (int i = tid; i < IN_DIM; i += 256)
            xrow[i] = x[(size_t)b * IN_DIM + i];
        __syncthreads();

        for (int j = tid; j < H0; j += 256) {
            float a = 0.f;
            for (int k = 0; k < IN_DIM; ++k)
                a = fmaf(xrow[k], W1[(size_t)k * H0 + j], a);
            h1row[j] = fmaxf(__fadd_rn(a, b1[j]), 0.f);
        }
        __syncthreads();

        if (tid < Dd) {
            float a = 0.f;
            const int col = tid * 8 + n;
            for (int j = 0; j < H0; ++j)
                a = fmaf(h1row[j], W2[(size_t)j * H1 + col], a);
            zrow[tid] = __fadd_rn(a, b2[col]);
        }
        __syncthreads();

        if (tid == 0) {
            float s2 = 0.f;
            for (int d = 0; d < Dd; ++d)
                s2 = __fadd_rn(s2, __fmul_rn(zrow[d], zrow[d]));
            z2_sh = s2;
        }
        __syncthreads();

        if (tid < Kc) {
            float e2 = 0.f, cr = 0.f;
            for (int d = 0; d < Dd; ++d) {
                const float ev = E[d * Kc + tid];
                e2 = __fadd_rn(e2, __fmul_rn(ev, ev));
                cr = fmaf(zrow[d], ev, cr);
            }
            dist[tid] = __fadd_rn(fmaf(-2.0f, cr, z2_sh), e2);
        }
        __syncthreads();

        if (tid == 0) {
            float best = dist[0]; int bi = 0;
            for (int k = 1; k < Kc; ++k)
                if (dist[k] < best) { best = dist[k]; bi = k; }
            kbest_sh = bi;
            idx_out[slot] = bi;
        }
        __syncthreads();

        if (tid < Dd)
            emb[(size_t)b * H1 + tid * 8 + n] = E[tid * Kc + kbest_sh];
        __syncthreads();
    }
}

// ---------------------------------------------------------------------------
// P[n,k,j] = sum_d E[d,k] * W3[d*8+n, j]
// ---------------------------------------------------------------------------
__global__ __launch_bounds__(128)
void build_P(const float* __restrict__ E, const float* __restrict__ W3,
             float* __restrict__ P)
{
    const int n = blockIdx.x >> 7;
    const int k = blockIdx.x & 127;
    const int j = threadIdx.x * 4;

    float4 acc = make_float4(0.f, 0.f, 0.f, 0.f);
#pragma unroll 8
    for (int d = 0; d < Dd; ++d) {
        const float e = __ldg(&E[d * Kc + k]);
        const float4 w = *reinterpret_cast<const float4*>(
            &W3[(size_t)(d * 8 + n) * H0 + j]);
        acc.x = fmaf(e, w.x, acc.x);
        acc.y = fmaf(e, w.y, acc.y);
        acc.z = fmaf(e, w.z, acc.z);
        acc.w = fmaf(e, w.w, acc.w);
    }
    *reinterpret_cast<float4*>(&P[((size_t)n * Kc + k) * H0 + j]) = acc;
}

// ---------------------------------------------------------------------------
// h3[b,j] = relu(b3[j] + sum_n P[n, idx[b,n], j])
// ---------------------------------------------------------------------------
__global__ __launch_bounds__(128, 8)
void decode_h3(const float* __restrict__ P, const int* __restrict__ idx,
               const float* __restrict__ b3, float* __restrict__ h3)
{
    __shared__ int sid[Nn];
    const int b = blockIdx.x;
    const int tid = threadIdx.x;
    if (tid < Nn) sid[tid] = idx[b * Nn + tid];
    __syncthreads();

    const int j = tid * 4;
    float4 acc = *reinterpret_cast<const float4*>(&b3[j]);
#pragma unroll
    for (int n = 0; n < Nn; ++n) {
        const float4 p = *reinterpret_cast<const float4*>(
            &P[((size_t)n * Kc + sid[n]) * H0 + j]);
        acc.x = __fadd_rn(acc.x, p.x);
        acc.y = __fadd_rn(acc.y, p.y);
        acc.z = __fadd_rn(acc.z, p.z);
        acc.w = __fadd_rn(acc.w, p.w);
    }
    acc.x = fmaxf(acc.x, 0.f);
    acc.y = fmaxf(acc.y, 0.f);
    acc.z = fmaxf(acc.z, 0.f);
    acc.w = fmaxf(acc.w, 0.f);
    *reinterpret_cast<float4*>(&h3[(size_t)b * H0 + j]) = acc;
}

// ---------------------------------------------------------------------------
extern "C" void kernel_launch(void* const* d_in, const int* in_sizes, int n_in,
                              void* d_out, int out_size)
{
    const float* x  = (const float*)d_in[0];
    const float* W1 = (const float*)d_in[1];
    const float* b1 = (const float*)d_in[2];
    const float* W2 = (const float*)d_in[3];
    const float* b2 = (const float*)d_in[4];
    const float* W3 = (const float*)d_in[5];
    const float* b3 = (const float*)d_in[6];
    const float* W4 = (const float*)d_in[7];
    const float* b4 = (const float*)d_in[8];
    const float* E  = (const float*)d_in[9];

    float* out   = (float*)d_out;
    float* recon = out;
    float* z_e   = out + (size_t)Bsz * IN_DIM;
    float* emb   = out + (size_t)Bsz * (IN_DIM + H1);

    void *p_h1, *p_h3, *p_P, *p_idx;
    cudaGetSymbolAddress(&p_h1,  g_h1);
    cudaGetSymbolAddress(&p_h3,  g_h3);
    cudaGetSymbolAddress(&p_P,   g_P);
    cudaGetSymbolAddress(&p_idx, g_idx);
    float* h1f = (float*)p_h1;
    float* h3f = (float*)p_h3;
    float* Pf  = (float*)p_P;
    int*   idxf = (int*)p_idx;

    static bool attr_set = false;
    if (!attr_set) {
        cudaFuncSetAttribute(vq_kernel,
                             cudaFuncAttributeMaxDynamicSharedMemorySize, VQ_SMEM);
        cudaFuncSetAttribute(gemm_tc<0>,
                             cudaFuncAttributeMaxDynamicSharedMemorySize, GEMM_SMEM);
        cudaFuncSetAttribute(gemm_tc<1>,
                             cudaFuncAttributeMaxDynamicSharedMemorySize, GEMM_SMEM);
        cudaFuncSetAttribute(gemm_tc<2>,
                             cudaFuncAttributeMaxDynamicSharedMemorySize, GEMM_SMEM);
        attr_set = true;
    }

    zero_nrep<<<1, 32>>>();
    build_P<<<Nn * Kc, 128>>>(E, W3, Pf);

    // GEMM1 (TC 3xTF32): h1' = relu(x @ W1 + b1)
    {
        dim3 grid(H0 / 64, Bsz / 128);
        gemm_tc<1><<<grid, 256, GEMM_SMEM>>>(x, W1, b1, h1f, Bsz, H0, IN_DIM);
    }
    // GEMM2 (TC 3xTF32): z_e' = h1' @ W2 + b2
    {
        dim3 grid(H1 / 64, Bsz / 128);
        gemm_tc<0><<<grid, 256, GEMM_SMEM>>>(h1f, W2, b2, z_e, Bsz, H1, H0);
    }
    // Fused VQ with gap flagging
    vq_kernel<<<Bsz / VQ_SAMPLES, 256, VQ_SMEM>>>(z_e, E, emb, idxf);

    // Exact repair of near-tie slots
    repair_kernel<<<1024, 256>>>(x, W1, b1, W2, b2, E, emb, idxf);

    // h3 via P-table gather-sum
    decode_h3<<<Bsz, 128>>>(Pf, idxf, b3, h3f);

    // GEMM4 (TC 3xTF32): recon = tanh(h3 @ W4 + b4)
    {
        dim3 grid((IN_DIM + 63) / 64, Bsz / 128);
        gemm_tc<2><<<grid, 256, GEMM_SMEM>>>(h3f, W4, b4, recon, Bsz, IN_DIM, H0);
    }
}